// round 1
// baseline (speedup 1.0000x reference)
#include <cuda_runtime.h>
#include <cstdint>
#include <math.h>

#define B_ 128
#define N_ 784
#define C_ 512
#define K_ 64

// scratch (no allocations allowed)
__device__ float g_an[K_ * C_];     // tf32-rounded normalized anchors
__device__ float g_lsS[B_ * N_];    // log S per (b,n)
__device__ float g_mix[B_ * N_];    // mixing weights

__device__ __forceinline__ float to_tf32(float x) {
    uint32_t u;
    asm("cvt.rna.tf32.f32 %0, %1;" : "=r"(u) : "f"(x));
    return __uint_as_float(u);
}

__device__ __forceinline__ void mma_tf32(float d[4], const float a[4], const float b[2]) {
    const uint32_t* A = reinterpret_cast<const uint32_t*>(a);
    const uint32_t* Bp = reinterpret_cast<const uint32_t*>(b);
    asm volatile(
        "mma.sync.aligned.m16n8k8.row.col.f32.tf32.tf32.f32 "
        "{%0,%1,%2,%3}, {%4,%5,%6,%7}, {%8,%9}, {%0,%1,%2,%3};\n"
        : "+f"(d[0]), "+f"(d[1]), "+f"(d[2]), "+f"(d[3])
        : "r"(A[0]), "r"(A[1]), "r"(A[2]), "r"(A[3]), "r"(Bp[0]), "r"(Bp[1]));
}

__device__ __forceinline__ float sigmoidf_(float t) {
    if (t >= 0.f) { float e = __expf(-t); return 1.f / (1.f + e); }
    float e = __expf(t); return e / (1.f + e);
}

// ---------------------------------------------------------------------------
// Kernel 1: normalize anchors, round to tf32. grid=64, block=128.
// ---------------------------------------------------------------------------
__global__ void __launch_bounds__(128) anchor_kernel(const float* __restrict__ kern) {
    int k = blockIdx.x;
    int tid = threadIdx.x;
    __shared__ float red[4];
    float s = 0.f;
    for (int c = tid; c < C_; c += 128) { float v = kern[k * C_ + c]; s += v * v; }
#pragma unroll
    for (int o = 16; o; o >>= 1) s += __shfl_xor_sync(0xffffffffu, s, o);
    if ((tid & 31) == 0) red[tid >> 5] = s;
    __syncthreads();
    float inv = 1.f / (sqrtf(red[0] + red[1] + red[2] + red[3]) + 1e-12f);
    for (int c = tid; c < C_; c += 128)
        g_an[k * C_ + c] = to_tf32(kern[k * C_ + c] * inv);
}

// ---------------------------------------------------------------------------
// Kernel 2: pass 1 — [128 rows x 512] x [512 x 64] tf32 MMA GEMM per block,
// fused row-norm + exp-sum epilogue -> log S. grid = 100352/128 = 784.
// Block: 256 threads = 8 warps in a 4(m) x 2(n) grid; each warp 32x32 tile.
// ---------------------------------------------------------------------------
__global__ void __launch_bounds__(256) pass1_kernel(const float* __restrict__ x) {
    __shared__ __align__(16) float sx[128][36];   // x tile (tf32), padded
    __shared__ __align__(16) float sa[64][36];    // anchor tile
    __shared__ float snp[8][128];                 // norm partials [seg][row]
    __shared__ float sinv[128];                   // 1/(||x||+eps)
    __shared__ float sSp[2][128];                 // exp-sum partials [wn][row]

    const int tid = threadIdx.x;
    const int lane = tid & 31, wid = tid >> 5;
    const int wm = wid & 3, wn = wid >> 2;
    const int g = lane >> 2, tig = lane & 3;
    const int seg = tid & 7, rq = tid >> 3;   // gmem->smem mapping

    const float* xg = x + (size_t)blockIdx.x * 128 * C_;

    float acc[2][4][4];
#pragma unroll
    for (int mt = 0; mt < 2; mt++)
#pragma unroll
        for (int nt = 0; nt < 4; nt++)
#pragma unroll
            for (int i = 0; i < 4; i++) acc[mt][nt][i] = 0.f;
    float nsq[4] = {0.f, 0.f, 0.f, 0.f};

    for (int kc = 0; kc < 16; kc++) {          // 16 chunks of 32 along C
        // load x tile [128][32] as float4, accumulate squares (pre-rounding)
#pragma unroll
        for (int i = 0; i < 4; i++) {
            int r = rq + 32 * i;
            float4 v = *reinterpret_cast<const float4*>(xg + (size_t)r * C_ + kc * 32 + seg * 4);
            nsq[i] += v.x * v.x + v.y * v.y + v.z * v.z + v.w * v.w;
            float4 t = make_float4(to_tf32(v.x), to_tf32(v.y), to_tf32(v.z), to_tf32(v.w));
            *reinterpret_cast<float4*>(&sx[r][seg * 4]) = t;
        }
        // load anchor tile [64][32]
#pragma unroll
        for (int i = 0; i < 2; i++) {
            int r = rq + 32 * i;
            float4 v = *reinterpret_cast<const float4*>(&g_an[r * C_ + kc * 32 + seg * 4]);
            *reinterpret_cast<float4*>(&sa[r][seg * 4]) = v;
        }
        __syncthreads();
#pragma unroll
        for (int ks = 0; ks < 4; ks++) {       // 4 k8 steps per chunk
            float af[2][4];
            float bf[4][2];
#pragma unroll
            for (int mt = 0; mt < 2; mt++) {
                int r0 = wm * 32 + mt * 16 + g;
                int c0 = ks * 8 + tig;
                af[mt][0] = sx[r0][c0];
                af[mt][1] = sx[r0 + 8][c0];
                af[mt][2] = sx[r0][c0 + 4];
                af[mt][3] = sx[r0 + 8][c0 + 4];
            }
#pragma unroll
            for (int nt = 0; nt < 4; nt++) {
                int n = wn * 32 + nt * 8 + g;
                int c0 = ks * 8 + tig;
                bf[nt][0] = sa[n][c0];
                bf[nt][1] = sa[n][c0 + 4];
            }
#pragma unroll
            for (int mt = 0; mt < 2; mt++)
#pragma unroll
                for (int nt = 0; nt < 4; nt++)
                    mma_tf32(acc[mt][nt], af[mt], bf[nt]);
        }
        __syncthreads();
    }

    // row norms
#pragma unroll
    for (int i = 0; i < 4; i++) snp[seg][rq + 32 * i] = nsq[i];
    __syncthreads();
    if (tid < 128) {
        float s2 = 0.f;
#pragma unroll
        for (int j = 0; j < 8; j++) s2 += snp[j][tid];
        sinv[tid] = 1.f / (sqrtf(s2) + 1e-12f);
    }
    __syncthreads();

    // epilogue: S_row = sum_k exp(20*s_k - 20)
#pragma unroll
    for (int mt = 0; mt < 2; mt++) {
        int r0 = wm * 32 + mt * 16 + g;
        float i0 = sinv[r0], i1 = sinv[r0 + 8];
        float p0 = 0.f, p1 = 0.f;
#pragma unroll
        for (int nt = 0; nt < 4; nt++) {
            p0 += __expf(20.f * acc[mt][nt][0] * i0 - 20.f)
                + __expf(20.f * acc[mt][nt][1] * i0 - 20.f);
            p1 += __expf(20.f * acc[mt][nt][2] * i1 - 20.f)
                + __expf(20.f * acc[mt][nt][3] * i1 - 20.f);
        }
        p0 += __shfl_xor_sync(0xffffffffu, p0, 1);
        p0 += __shfl_xor_sync(0xffffffffu, p0, 2);
        p1 += __shfl_xor_sync(0xffffffffu, p1, 1);
        p1 += __shfl_xor_sync(0xffffffffu, p1, 2);
        if (tig == 0) { sSp[wn][r0] = p0; sSp[wn][r0 + 8] = p1; }
    }
    __syncthreads();
    if (tid < 128) {
        g_lsS[(size_t)blockIdx.x * 128 + tid] = __logf(sSp[0][tid] + sSp[1][tid]);
    }
}

// ---------------------------------------------------------------------------
// Kernel 3: per-batch Sinkhorn scalar v (10 iters) + mixing weights.
// grid = 128, block = 256.
// ---------------------------------------------------------------------------
__global__ void __launch_bounds__(256) vsolve_kernel() {
    __shared__ float sl[N_];
    __shared__ float red[8];
    __shared__ float vsh;
    int b = blockIdx.x, tid = threadIdx.x;
    for (int n = tid; n < N_; n += 256) sl[n] = g_lsS[b * N_ + n];
    __syncthreads();
    float v = 0.f;
    const float logmu = logf(0.5f);
    const float logn = logf((float)N_);
    for (int it = 0; it < 10; ++it) {
        float part = 0.f;
        for (int n = tid; n < N_; n += 256) part += sigmoidf_(sl[n] + 10.f * v);
#pragma unroll
        for (int o = 16; o; o >>= 1) part += __shfl_xor_sync(0xffffffffu, part, o);
        if ((tid & 31) == 0) red[tid >> 5] = part;
        __syncthreads();
        if (tid == 0) {
            float s = 0.f;
#pragma unroll
            for (int j = 0; j < 8; j++) s += red[j];
            float m = __logf(s) - logn;
            vsh = v + 0.1f * (logmu - m);
        }
        __syncthreads();
        v = vsh;
    }
    for (int n = tid; n < N_; n += 256)
        g_mix[b * N_ + n] = 2.f * sigmoidf_(sl[n] + 10.f * v);
}

// ---------------------------------------------------------------------------
// Kernel 4: pass 2 — weighted mean over n. grid = (4 c-chunks, 128 b), 128 thr.
// ---------------------------------------------------------------------------
__global__ void __launch_bounds__(128) pool_kernel(const float* __restrict__ x,
                                                   float* __restrict__ out) {
    __shared__ float sm[N_];
    int b = blockIdx.y;
    int c = blockIdx.x * 128 + threadIdx.x;
    for (int n = threadIdx.x; n < N_; n += 128) sm[n] = g_mix[b * N_ + n];
    __syncthreads();
    const float* xb = x + (size_t)b * N_ * C_ + c;
    float acc[8];
#pragma unroll
    for (int j = 0; j < 8; j++) acc[j] = 0.f;
    for (int n = 0; n < N_; n += 8) {        // 784 = 98*8
        float xv[8], mv[8];
#pragma unroll
        for (int j = 0; j < 8; j++) xv[j] = xb[(size_t)(n + j) * C_];
#pragma unroll
        for (int j = 0; j < 8; j++) mv[j] = sm[n + j];
#pragma unroll
        for (int j = 0; j < 8; j++) acc[j] += mv[j] * xv[j];
    }
    float t = ((acc[0] + acc[1]) + (acc[2] + acc[3]))
            + ((acc[4] + acc[5]) + (acc[6] + acc[7]));
    out[b * C_ + c] = t * (1.f / (float)N_);
}

// ---------------------------------------------------------------------------
extern "C" void kernel_launch(void* const* d_in, const int* in_sizes, int n_in,
                              void* d_out, int out_size) {
    const float* bow = (const float*)d_in[0];
    const float* kern = (const float*)d_in[1];
    if (n_in >= 2 && in_sizes[0] < in_sizes[1]) {  // defensive: pick by size
        const float* t = bow; bow = kern; kern = t;
    }
    anchor_kernel<<<K_, 128>>>(kern);
    pass1_kernel<<<(B_ * N_) / 128, 256>>>(bow);
    vsolve_kernel<<<B_, 256>>>();
    pool_kernel<<<dim3(C_ / 128, B_), 128>>>(bow, (float*)d_out);
}

// round 2
// speedup vs baseline: 1.2577x; 1.2577x over previous
#include <cuda_runtime.h>
#include <cstdint>
#include <math.h>

#define B_ 128
#define N_ 784
#define C_ 512
#define K_ 64
#define NSPLIT 16
#define NPER 49   // 784/16

// scratch (no allocations allowed)
__device__ float g_an[K_ * C_];                    // tf32-rounded normalized anchors
__device__ float g_lsS[B_ * N_];                   // log S per (b,n)
__device__ float g_mix[B_ * N_];                   // mixing weights
__device__ float4 g_part[NSPLIT * B_ * C_ / 4];    // pool partials (4 MB)

__device__ __forceinline__ float to_tf32(float x) {
    uint32_t u;
    asm("cvt.rna.tf32.f32 %0, %1;" : "=r"(u) : "f"(x));
    return __uint_as_float(u);
}

__device__ __forceinline__ void mma_tf32(float d[4], const float a[4], const float b[2]) {
    const uint32_t* A = reinterpret_cast<const uint32_t*>(a);
    const uint32_t* Bp = reinterpret_cast<const uint32_t*>(b);
    asm volatile(
        "mma.sync.aligned.m16n8k8.row.col.f32.tf32.tf32.f32 "
        "{%0,%1,%2,%3}, {%4,%5,%6,%7}, {%8,%9}, {%0,%1,%2,%3};\n"
        : "+f"(d[0]), "+f"(d[1]), "+f"(d[2]), "+f"(d[3])
        : "r"(A[0]), "r"(A[1]), "r"(A[2]), "r"(A[3]), "r"(Bp[0]), "r"(Bp[1]));
}

__device__ __forceinline__ float sigmoidf_(float t) {
    if (t >= 0.f) { float e = __expf(-t); return 1.f / (1.f + e); }
    float e = __expf(t); return e / (1.f + e);
}

// ---------------------------------------------------------------------------
// Kernel 1: normalize anchors, round to tf32. grid=64, block=128.
// ---------------------------------------------------------------------------
__global__ void __launch_bounds__(128) anchor_kernel(const float* __restrict__ kern) {
    int k = blockIdx.x;
    int tid = threadIdx.x;
    __shared__ float red[4];
    float s = 0.f;
    for (int c = tid; c < C_; c += 128) { float v = kern[k * C_ + c]; s += v * v; }
#pragma unroll
    for (int o = 16; o; o >>= 1) s += __shfl_xor_sync(0xffffffffu, s, o);
    if ((tid & 31) == 0) red[tid >> 5] = s;
    __syncthreads();
    float inv = 1.f / (sqrtf(red[0] + red[1] + red[2] + red[3]) + 1e-12f);
    for (int c = tid; c < C_; c += 128)
        g_an[k * C_ + c] = to_tf32(kern[k * C_ + c] * inv);
}

// ---------------------------------------------------------------------------
// Kernel 2: pass 1 — [128 rows x 512] x [512 x 64] tf32 MMA GEMM per block,
// fused row-norm + exp-sum epilogue -> log S. grid = 100352/128 = 784.
// Register-prefetch software pipeline: next chunk's LDGs issue before MMAs.
// ---------------------------------------------------------------------------
__global__ void __launch_bounds__(256) pass1_kernel(const float* __restrict__ x) {
    __shared__ __align__(16) float sx[128][36];   // x tile (tf32), padded
    __shared__ __align__(16) float sa[64][36];    // anchor tile
    __shared__ float snp[8][128];                 // norm partials [seg][row]
    __shared__ float sinv[128];                   // 1/(||x||+eps)
    __shared__ float sSp[2][128];                 // exp-sum partials [wn][row]

    const int tid = threadIdx.x;
    const int lane = tid & 31, wid = tid >> 5;
    const int wm = wid & 3, wn = wid >> 2;
    const int g = lane >> 2, tig = lane & 3;
    const int seg = tid & 7, rq = tid >> 3;   // gmem->smem mapping

    const float* xg = x + (size_t)blockIdx.x * 128 * C_;

    float acc[2][4][4];
#pragma unroll
    for (int mt = 0; mt < 2; mt++)
#pragma unroll
        for (int nt = 0; nt < 4; nt++)
#pragma unroll
            for (int i = 0; i < 4; i++) acc[mt][nt][i] = 0.f;
    float nsq[4] = {0.f, 0.f, 0.f, 0.f};

    float4 rx[4], ra[2];
    // prologue: load chunk 0
#pragma unroll
    for (int i = 0; i < 4; i++)
        rx[i] = *reinterpret_cast<const float4*>(xg + (size_t)(rq + 32 * i) * C_ + seg * 4);
#pragma unroll
    for (int i = 0; i < 2; i++)
        ra[i] = *reinterpret_cast<const float4*>(&g_an[(rq + 32 * i) * C_ + seg * 4]);

#pragma unroll 1
    for (int kc = 0; kc < 16; kc++) {
        // stage registers -> smem (with tf32 round + norm accumulation)
#pragma unroll
        for (int i = 0; i < 4; i++) {
            float4 v = rx[i];
            nsq[i] += v.x * v.x + v.y * v.y + v.z * v.z + v.w * v.w;
            float4 t = make_float4(to_tf32(v.x), to_tf32(v.y), to_tf32(v.z), to_tf32(v.w));
            *reinterpret_cast<float4*>(&sx[rq + 32 * i][seg * 4]) = t;
        }
#pragma unroll
        for (int i = 0; i < 2; i++)
            *reinterpret_cast<float4*>(&sa[rq + 32 * i][seg * 4]) = ra[i];
        __syncthreads();

        // prefetch next chunk (LDGs overlap the MMA section below)
        if (kc < 15) {
            int off = (kc + 1) * 32 + seg * 4;
#pragma unroll
            for (int i = 0; i < 4; i++)
                rx[i] = *reinterpret_cast<const float4*>(xg + (size_t)(rq + 32 * i) * C_ + off);
#pragma unroll
            for (int i = 0; i < 2; i++)
                ra[i] = *reinterpret_cast<const float4*>(&g_an[(rq + 32 * i) * C_ + off]);
        }

#pragma unroll
        for (int ks = 0; ks < 4; ks++) {
            float af[2][4];
            float bf[4][2];
#pragma unroll
            for (int mt = 0; mt < 2; mt++) {
                int r0 = wm * 32 + mt * 16 + g;
                int c0 = ks * 8 + tig;
                af[mt][0] = sx[r0][c0];
                af[mt][1] = sx[r0 + 8][c0];
                af[mt][2] = sx[r0][c0 + 4];
                af[mt][3] = sx[r0 + 8][c0 + 4];
            }
#pragma unroll
            for (int nt = 0; nt < 4; nt++) {
                int n = wn * 32 + nt * 8 + g;
                int c0 = ks * 8 + tig;
                bf[nt][0] = sa[n][c0];
                bf[nt][1] = sa[n][c0 + 4];
            }
#pragma unroll
            for (int mt = 0; mt < 2; mt++)
#pragma unroll
                for (int nt = 0; nt < 4; nt++)
                    mma_tf32(acc[mt][nt], af[mt], bf[nt]);
        }
        __syncthreads();
    }

    // row norms
#pragma unroll
    for (int i = 0; i < 4; i++) snp[seg][rq + 32 * i] = nsq[i];
    __syncthreads();
    if (tid < 128) {
        float s2 = 0.f;
#pragma unroll
        for (int j = 0; j < 8; j++) s2 += snp[j][tid];
        sinv[tid] = 1.f / (sqrtf(s2) + 1e-12f);
    }
    __syncthreads();

    // epilogue: S_row = sum_k exp(20*s_k - 20)
#pragma unroll
    for (int mt = 0; mt < 2; mt++) {
        int r0 = wm * 32 + mt * 16 + g;
        float i0 = sinv[r0], i1 = sinv[r0 + 8];
        float p0 = 0.f, p1 = 0.f;
#pragma unroll
        for (int nt = 0; nt < 4; nt++) {
            p0 += __expf(20.f * acc[mt][nt][0] * i0 - 20.f)
                + __expf(20.f * acc[mt][nt][1] * i0 - 20.f);
            p1 += __expf(20.f * acc[mt][nt][2] * i1 - 20.f)
                + __expf(20.f * acc[mt][nt][3] * i1 - 20.f);
        }
        p0 += __shfl_xor_sync(0xffffffffu, p0, 1);
        p0 += __shfl_xor_sync(0xffffffffu, p0, 2);
        p1 += __shfl_xor_sync(0xffffffffu, p1, 1);
        p1 += __shfl_xor_sync(0xffffffffu, p1, 2);
        if (tig == 0) { sSp[wn][r0] = p0; sSp[wn][r0 + 8] = p1; }
    }
    __syncthreads();
    if (tid < 128) {
        g_lsS[(size_t)blockIdx.x * 128 + tid] = __logf(sSp[0][tid] + sSp[1][tid]);
    }
}

// ---------------------------------------------------------------------------
// Kernel 3: per-batch Sinkhorn scalar v (10 iters) + mixing weights.
// ---------------------------------------------------------------------------
__global__ void __launch_bounds__(256) vsolve_kernel() {
    __shared__ float sl[N_];
    __shared__ float red[8];
    __shared__ float vsh;
    int b = blockIdx.x, tid = threadIdx.x;
    for (int n = tid; n < N_; n += 256) sl[n] = g_lsS[b * N_ + n];
    __syncthreads();
    float v = 0.f;
    const float logmu = logf(0.5f);
    const float logn = logf((float)N_);
    for (int it = 0; it < 10; ++it) {
        float part = 0.f;
        for (int n = tid; n < N_; n += 256) part += sigmoidf_(sl[n] + 10.f * v);
#pragma unroll
        for (int o = 16; o; o >>= 1) part += __shfl_xor_sync(0xffffffffu, part, o);
        if ((tid & 31) == 0) red[tid >> 5] = part;
        __syncthreads();
        if (tid == 0) {
            float s = 0.f;
#pragma unroll
            for (int j = 0; j < 8; j++) s += red[j];
            float m = __logf(s) - logn;
            vsh = v + 0.1f * (logmu - m);
        }
        __syncthreads();
        v = vsh;
    }
    for (int n = tid; n < N_; n += 256)
        g_mix[b * N_ + n] = 2.f * sigmoidf_(sl[n] + 10.f * v);
}

// ---------------------------------------------------------------------------
// Kernel 4a: pool stage 1 — each block = (nsplit, batch) slice of 49 n-rows,
// float4 loads, 7 rotating accumulators. Batch order reversed so the tail of
// pass1's working set (still L2-resident) is consumed first.
// grid = (NSPLIT, B_), block = 128 (one float4 column each).
// ---------------------------------------------------------------------------
__global__ void __launch_bounds__(128) pool1_kernel(const float* __restrict__ x) {
    __shared__ float sm[NPER];
    const int ns = blockIdx.x;
    const int b = B_ - 1 - blockIdx.y;        // reverse order for L2 reuse
    const int tid = threadIdx.x;

    if (tid < NPER) sm[tid] = g_mix[b * N_ + ns * NPER + tid];
    __syncthreads();

    const float4* xb = reinterpret_cast<const float4*>(
        x + (size_t)b * N_ * C_ + (size_t)(ns * NPER) * C_) + tid;

    float4 acc[7];
#pragma unroll
    for (int j = 0; j < 7; j++) acc[j] = make_float4(0.f, 0.f, 0.f, 0.f);

#pragma unroll 1
    for (int n0 = 0; n0 < NPER; n0 += 7) {
        float4 v[7];
        float m[7];
#pragma unroll
        for (int j = 0; j < 7; j++) v[j] = xb[(size_t)(n0 + j) * (C_ / 4)];
#pragma unroll
        for (int j = 0; j < 7; j++) m[j] = sm[n0 + j];
#pragma unroll
        for (int j = 0; j < 7; j++) {
            acc[j].x += m[j] * v[j].x;
            acc[j].y += m[j] * v[j].y;
            acc[j].z += m[j] * v[j].z;
            acc[j].w += m[j] * v[j].w;
        }
    }
    float4 t;
    t.x = ((acc[0].x + acc[1].x) + (acc[2].x + acc[3].x)) + ((acc[4].x + acc[5].x) + acc[6].x);
    t.y = ((acc[0].y + acc[1].y) + (acc[2].y + acc[3].y)) + ((acc[4].y + acc[5].y) + acc[6].y);
    t.z = ((acc[0].z + acc[1].z) + (acc[2].z + acc[3].z)) + ((acc[4].z + acc[5].z) + acc[6].z);
    t.w = ((acc[0].w + acc[1].w) + (acc[2].w + acc[3].w)) + ((acc[4].w + acc[5].w) + acc[6].w);
    g_part[(size_t)ns * (B_ * C_ / 4) + b * (C_ / 4) + tid] = t;
}

// ---------------------------------------------------------------------------
// Kernel 4b: pool stage 2 — reduce 16 partials, scale by 1/N.
// grid = 64, block = 256: one float4 output element per thread.
// ---------------------------------------------------------------------------
__global__ void __launch_bounds__(256) pool2_kernel(float* __restrict__ out) {
    int i = blockIdx.x * 256 + threadIdx.x;   // 0 .. 16383
    float4 s = make_float4(0.f, 0.f, 0.f, 0.f);
#pragma unroll
    for (int p = 0; p < NSPLIT; p++) {
        float4 v = g_part[(size_t)p * (B_ * C_ / 4) + i];
        s.x += v.x; s.y += v.y; s.z += v.z; s.w += v.w;
    }
    const float inv = 1.f / (float)N_;
    s.x *= inv; s.y *= inv; s.z *= inv; s.w *= inv;
    reinterpret_cast<float4*>(out)[i] = s;
}

// ---------------------------------------------------------------------------
extern "C" void kernel_launch(void* const* d_in, const int* in_sizes, int n_in,
                              void* d_out, int out_size) {
    const float* bow = (const float*)d_in[0];
    const float* kern = (const float*)d_in[1];
    if (n_in >= 2 && in_sizes[0] < in_sizes[1]) {  // defensive: pick by size
        const float* t = bow; bow = kern; kern = t;
    }
    anchor_kernel<<<K_, 128>>>(kern);
    pass1_kernel<<<(B_ * N_) / 128, 256>>>(bow);
    vsolve_kernel<<<B_, 256>>>();
    pool1_kernel<<<dim3(NSPLIT, B_), 128>>>(bow);
    pool2_kernel<<<64, 256>>>((float*)d_out);
}

// round 6
// speedup vs baseline: 1.5603x; 1.2406x over previous
#include <cuda_runtime.h>
#include <cuda_bf16.h>
#include <cstdint>
#include <math.h>

#define B_ 128
#define N_ 784
#define C_ 512
#define K_ 64
#define NSPLIT 8
#define NPER 98   // 784/8

// A/B smem tiles: 64-col chunks, rows padded to 72 bf16 (144B) for conflict-free LDSM
#define APAD 72

// ---------------- scratch (no allocations allowed) -------------------------
// anchors pre-normalized to bf16, stored per-chunk in the exact padded smem layout
__device__ __align__(16) __nv_bfloat16 g_an_bf16[8][K_][APAD];   // 73728 B
__device__ float g_lsS[B_ * N_];                   // log S per (b,n)
__device__ float g_mix[B_ * N_];                   // mixing weights
__device__ float4 g_part[NSPLIT * B_ * C_ / 4];    // pool partials (2 MB)

__device__ __forceinline__ uint32_t smem_u32(const void* p) {
    uint32_t a;
    asm("{ .reg .u64 t; cvta.to.shared.u64 t, %1; cvt.u32.u64 %0, t; }" : "=r"(a) : "l"(p));
    return a;
}

#define LDSM4(r0, r1, r2, r3, addr) \
    asm volatile("ldmatrix.sync.aligned.m8n8.x4.shared.b16 {%0,%1,%2,%3}, [%4];" \
                 : "=r"(r0), "=r"(r1), "=r"(r2), "=r"(r3) : "r"(addr))

__device__ __forceinline__ void mma_bf16(float d[4], const uint32_t a[4],
                                         uint32_t b0, uint32_t b1) {
    asm volatile(
        "mma.sync.aligned.m16n8k16.row.col.f32.bf16.bf16.f32 "
        "{%0,%1,%2,%3}, {%4,%5,%6,%7}, {%8,%9}, {%0,%1,%2,%3};"
        : "+f"(d[0]), "+f"(d[1]), "+f"(d[2]), "+f"(d[3])
        : "r"(a[0]), "r"(a[1]), "r"(a[2]), "r"(a[3]), "r"(b0), "r"(b1));
}

__device__ __forceinline__ float sigmoidf_(float t) {
    if (t >= 0.f) { float e = __expf(-t); return 1.f / (1.f + e); }
    float e = __expf(t); return e / (1.f + e);
}

// ---------------------------------------------------------------------------
// Kernel 1: normalize anchors -> bf16 in padded per-chunk tile layout.
// grid=64 (one anchor per block), block=128.
// ---------------------------------------------------------------------------
__global__ void __launch_bounds__(128) anchor_kernel(const float* __restrict__ kern) {
    int k = blockIdx.x;
    int tid = threadIdx.x;
    __shared__ float red[4];
    float s = 0.f;
    for (int c = tid; c < C_; c += 128) { float v = kern[k * C_ + c]; s += v * v; }
#pragma unroll
    for (int o = 16; o; o >>= 1) s += __shfl_xor_sync(0xffffffffu, s, o);
    if ((tid & 31) == 0) red[tid >> 5] = s;
    __syncthreads();
    float inv = 1.f / (sqrtf(red[0] + red[1] + red[2] + red[3]) + 1e-12f);
    for (int p = tid; p < 256; p += 128) {     // 256 col pairs
        int c = p * 2;
        int kc = c >> 6, cc = c & 63;
        __nv_bfloat162 h = __floats2bfloat162_rn(kern[k * C_ + c] * inv,
                                                 kern[k * C_ + c + 1] * inv);
        *reinterpret_cast<__nv_bfloat162*>(&g_an_bf16[kc][k][cc]) = h;
    }
}

// ---------------------------------------------------------------------------
// Kernel 2: pass 1 — bf16 mma.m16n8k16 + ldmatrix GEMM [128x512]x[512x64],
// fused row-norm + exp-sum epilogue -> log S. grid=784, block=256 (8 warps).
// Warp w owns rows [16w,16w+16) x all 64 anchors. Register-prefetch pipeline.
// ---------------------------------------------------------------------------
__global__ void __launch_bounds__(256) pass1_kernel(const float* __restrict__ x) {
    __shared__ __align__(16) __nv_bfloat16 sx[128][APAD];   // 18432 B
    __shared__ __align__(16) __nv_bfloat16 sa[K_][APAD];    //  9216 B
    __shared__ float sinv[128];

    const int tid = threadIdx.x;
    const int lane = tid & 31, wid = tid >> 5;
    const int seg = tid & 15, rowq = tid >> 4;   // staging map: 16 segs x 16 rows
    const int wr = wid * 16;

    const uint32_t sxb = smem_u32(sx);
    const uint32_t sab = smem_u32(sa);
    // ldmatrix per-lane address components
    const uint32_t a_row = (uint32_t)(wr + (lane & 15));
    const uint32_t a_colb = (uint32_t)((lane >> 4) << 3);
    const uint32_t b_rowo = (uint32_t)((lane & 7) + ((lane >> 4) << 3));
    const uint32_t b_colo = (uint32_t)(lane & 8);

    const float* xg = x + (size_t)blockIdx.x * 128 * C_;
    const uint4* an4 = reinterpret_cast<const uint4*>(g_an_bf16);  // 576 uint4/chunk

    float acc[8][4];
#pragma unroll
    for (int t = 0; t < 8; t++)
#pragma unroll
        for (int i = 0; i < 4; i++) acc[t][i] = 0.f;
    float nsq[8];
#pragma unroll
    for (int j = 0; j < 8; j++) nsq[j] = 0.f;

    float4 rx[8];
    uint4 rb[3];
    // prologue: chunk 0
#pragma unroll
    for (int j = 0; j < 8; j++)
        rx[j] = *reinterpret_cast<const float4*>(xg + (size_t)(rowq + 16 * j) * C_ + seg * 4);
#pragma unroll
    for (int i = 0; i < 3; i++) {
        int idx = tid + 256 * i;
        if (idx < 576) rb[i] = an4[idx];
    }

#pragma unroll 1
    for (int kc = 0; kc < 8; kc++) {
        // stage A (convert fp32->bf16, accumulate norms) and B
#pragma unroll
        for (int j = 0; j < 8; j++) {
            float4 v = rx[j];
            nsq[j] += v.x * v.x + v.y * v.y + v.z * v.z + v.w * v.w;
            __nv_bfloat162 h0 = __floats2bfloat162_rn(v.x, v.y);
            __nv_bfloat162 h1 = __floats2bfloat162_rn(v.z, v.w);
            uint2 u;
            u.x = *reinterpret_cast<uint32_t*>(&h0);
            u.y = *reinterpret_cast<uint32_t*>(&h1);
            *reinterpret_cast<uint2*>(&sx[rowq + 16 * j][seg * 4]) = u;
        }
#pragma unroll
        for (int i = 0; i < 3; i++) {
            int idx = tid + 256 * i;
            if (idx < 576) reinterpret_cast<uint4*>(sa)[idx] = rb[i];
        }
        __syncthreads();

        // prefetch next chunk (overlaps MMA section)
        if (kc < 7) {
            int co = (kc + 1) * 64 + seg * 4;
#pragma unroll
            for (int j = 0; j < 8; j++)
                rx[j] = *reinterpret_cast<const float4*>(xg + (size_t)(rowq + 16 * j) * C_ + co);
#pragma unroll
            for (int i = 0; i < 3; i++) {
                int idx = tid + 256 * i;
                if (idx < 576) rb[i] = an4[(kc + 1) * 576 + idx];
            }
        }

        // MMA: 4 k16 steps
#pragma unroll
        for (int ks = 0; ks < 4; ks++) {
            uint32_t a[4];
            LDSM4(a[0], a[1], a[2], a[3],
                  sxb + a_row * (APAD * 2) + (ks * 16 + a_colb) * 2);
#pragma unroll
            for (int nt = 0; nt < 4; nt++) {
                uint32_t b0, b1, b2, b3;
                LDSM4(b0, b1, b2, b3,
                      sab + (nt * 16 + b_rowo) * (APAD * 2) + (ks * 16 + b_colo) * 2);
                mma_bf16(acc[2 * nt], a, b0, b1);
                mma_bf16(acc[2 * nt + 1], a, b2, b3);
            }
        }
        __syncthreads();
    }

    // row norms: overlay partials on sa (done with MMA smem)
    float* snp = reinterpret_cast<float*>(sa);   // [16][128]
#pragma unroll
    for (int j = 0; j < 8; j++) snp[seg * 128 + rowq + 16 * j] = nsq[j];
    __syncthreads();
    if (tid < 128) {
        float s2 = 0.f;
#pragma unroll
        for (int j = 0; j < 16; j++) s2 += snp[j * 128 + tid];
        sinv[tid] = 20.f / (sqrtf(s2) + 1e-12f);
    }
    __syncthreads();

    // epilogue: per-warp rows wr+g and wr+8+g; n fully covered within warp
    {
        const int g = lane >> 2;
        const int r0 = wr + g, r1 = wr + 8 + g;
        const float i0 = sinv[r0], i1 = sinv[r1];
        float p0 = 0.f, p1 = 0.f;
#pragma unroll
        for (int t = 0; t < 8; t++) {
            p0 += __expf(fmaf(i0, acc[t][0], -20.f)) + __expf(fmaf(i0, acc[t][1], -20.f));
            p1 += __expf(fmaf(i1, acc[t][2], -20.f)) + __expf(fmaf(i1, acc[t][3], -20.f));
        }
        p0 += __shfl_xor_sync(0xffffffffu, p0, 1);
        p0 += __shfl_xor_sync(0xffffffffu, p0, 2);
        p1 += __shfl_xor_sync(0xffffffffu, p1, 1);
        p1 += __shfl_xor_sync(0xffffffffu, p1, 2);
        if ((lane & 3) == 0) {
            g_lsS[(size_t)blockIdx.x * 128 + r0] = __logf(p0);
            g_lsS[(size_t)blockIdx.x * 128 + r1] = __logf(p1);
        }
    }
}

// ---------------------------------------------------------------------------
// Kernel 3: per-batch Sinkhorn scalar v (10 iters) + mixing weights.
// ---------------------------------------------------------------------------
__global__ void __launch_bounds__(256) vsolve_kernel() {
    __shared__ float sl[N_];
    __shared__ float red[8];
    __shared__ float vsh;
    int b = blockIdx.x, tid = threadIdx.x;
    for (int n = tid; n < N_; n += 256) sl[n] = g_lsS[b * N_ + n];
    __syncthreads();
    float v = 0.f;
    const float logmu = logf(0.5f);
    const float logn = logf((float)N_);
    for (int it = 0; it < 10; ++it) {
        float part = 0.f;
        for (int n = tid; n < N_; n += 256) part += sigmoidf_(sl[n] + 10.f * v);
#pragma unroll
        for (int o = 16; o; o >>= 1) part += __shfl_xor_sync(0xffffffffu, part, o);
        if ((tid & 31) == 0) red[tid >> 5] = part;
        __syncthreads();
        if (tid == 0) {
            float s = 0.f;
#pragma unroll
            for (int j = 0; j < 8; j++) s += red[j];
            float m = __logf(s) - logn;
            vsh = v + 0.1f * (logmu - m);
        }
        __syncthreads();
        v = vsh;
    }
    for (int n = tid; n < N_; n += 256)
        g_mix[b * N_ + n] = 2.f * sigmoidf_(sl[n] + 10.f * v);
}

// ---------------------------------------------------------------------------
// Kernel 4a: pool stage 1 — (nsplit, batch) slice of 98 n-rows, float4 loads,
// 14-deep load batches (MLP), reversed batch order for L2 reuse of pass1 tail.
// grid = (NSPLIT, B_), block = 128.
// ---------------------------------------------------------------------------
__global__ void __launch_bounds__(128) pool1_kernel(const float* __restrict__ x) {
    __shared__ float sm[NPER];
    const int ns = blockIdx.x;
    const int b = B_ - 1 - blockIdx.y;
    const int tid = threadIdx.x;

    if (tid < NPER) sm[tid] = g_mix[b * N_ + ns * NPER + tid];
    __syncthreads();

    const float4* xb = reinterpret_cast<const float4*>(
        x + (size_t)b * N_ * C_ + (size_t)(ns * NPER) * C_) + tid;

    float4 acc[7];
#pragma unroll
    for (int j = 0; j < 7; j++) acc[j] = make_float4(0.f, 0.f, 0.f, 0.f);

#pragma unroll 1
    for (int n0 = 0; n0 < NPER; n0 += 14) {   // 98 = 7*14
        float4 v[14];
        float m[14];
#pragma unroll
        for (int j = 0; j < 14; j++) v[j] = xb[(size_t)(n0 + j) * (C_ / 4)];
#pragma unroll
        for (int j = 0; j < 14; j++) m[j] = sm[n0 + j];
#pragma unroll
        for (int j = 0; j < 7; j++) {
            acc[j].x += m[j] * v[j].x; acc[j].y += m[j] * v[j].y;
            acc[j].z += m[j] * v[j].z; acc[j].w += m[j] * v[j].w;
        }
#pragma unroll
        for (int j = 0; j < 7; j++) {
            acc[j].x += m[j + 7] * v[j + 7].x; acc[j].y += m[j + 7] * v[j + 7].y;
            acc[j].z += m[j + 7] * v[j + 7].z; acc[j].w += m[j + 7] * v[j + 7].w;
        }
    }
    float4 t;
    t.x = ((acc[0].x + acc[1].x) + (acc[2].x + acc[3].x)) + ((acc[4].x + acc[5].x) + acc[6].x);
    t.y = ((acc[0].y + acc[1].y) + (acc[2].y + acc[3].y)) + ((acc[4].y + acc[5].y) + acc[6].y);
    t.z = ((acc[0].z + acc[1].z) + (acc[2].z + acc[3].z)) + ((acc[4].z + acc[5].z) + acc[6].z);
    t.w = ((acc[0].w + acc[1].w) + (acc[2].w + acc[3].w)) + ((acc[4].w + acc[5].w) + acc[6].w);
    g_part[(size_t)ns * (B_ * C_ / 4) + b * (C_ / 4) + tid] = t;
}

// ---------------------------------------------------------------------------
// Kernel 4b: pool stage 2 — reduce NSPLIT partials, scale by 1/N.
// ---------------------------------------------------------------------------
__global__ void __launch_bounds__(256) pool2_kernel(float* __restrict__ out) {
    int i = blockIdx.x * 256 + threadIdx.x;   // 0 .. 16383
    float4 s = make_float4(0.f, 0.f, 0.f, 0.f);
#pragma unroll
    for (int p = 0; p < NSPLIT; p++) {
        float4 v = g_part[(size_t)p * (B_ * C_ / 4) + i];
        s.x += v.x; s.y += v.y; s.z += v.z; s.w += v.w;
    }
    const float inv = 1.f / (float)N_;
    s.x *= inv; s.y *= inv; s.z *= inv; s.w *= inv;
    reinterpret_cast<float4*>(out)[i] = s;
}

// ---------------------------------------------------------------------------
extern "C" void kernel_launch(void* const* d_in, const int* in_sizes, int n_in,
                              void* d_out, int out_size) {
    const float* bow = (const float*)d_in[0];
    const float* kern = (const float*)d_in[1];
    if (n_in >= 2 && in_sizes[0] < in_sizes[1]) {  // defensive: pick by size
        const float* t = bow; bow = kern; kern = t;
    }
    anchor_kernel<<<K_, 128>>>(kern);
    pass1_kernel<<<(B_ * N_) / 128, 256>>>(bow);
    vsolve_kernel<<<B_, 256>>>();
    pool1_kernel<<<dim3(NSPLIT, B_), 128>>>(bow);
    pool2_kernel<<<64, 256>>>((float*)d_out);
}